// round 14
// baseline (speedup 1.0000x reference)
#include <cuda_runtime.h>
#include <cuda_fp16.h>
#include <math.h>
#include <stdint.h>

typedef unsigned long long ull;

// Problem dims (fixed)
#define BB 2
#define TT 2048
#define DD 2048
#define HHN 16
#define KKD 128
#define VVD 128
#define BT  (BB*TT)     // 4096
#define HK  (HHN*KKD)   // 2048
#define NG8 256         // 8-step groups

// Scratch (device globals: no allocation allowed)
__device__ float g_q[BT*HK];
__device__ float g_k[BT*HK];
__device__ float g_v[BT*HK];
__device__ float g_alpha[BT*HHN];
__device__ float g_beta[BT*HHN];
__device__ float g_kq[BT*HHN];              // k_t . q_t
__device__ float g_cd[BB*HHN*NG8*56];       // per group: 28 k_i.k_j (i<j) then 28 k_i.q_j (i<j)
__device__ __half g_xh[BT*DD];
__device__ __half g_wqh[HK*DD];
__device__ __half g_wkh[HK*DD];
__device__ __half g_wvh[HK*DD];

// upper-triangle index for i<j in 0..7
#define TRI(i,j) (7*(i) - (i)*((i)-1)/2 + ((j)-(i)-1))

// ---------------------------------------------------------------------------
// helpers
// ---------------------------------------------------------------------------
__device__ __forceinline__ uint32_t smem_u32(const void* p) {
    uint32_t a;
    asm("{ .reg .u64 t; cvta.to.shared.u64 t, %1; cvt.u32.u64 %0, t; }" : "=r"(a) : "l"(p));
    return a;
}
__device__ __forceinline__ void cp16(uint32_t dst, const void* src) {
    asm volatile("cp.async.cg.shared.global [%0], [%1], 16;" :: "r"(dst), "l"(src));
}
#define CP_COMMIT() asm volatile("cp.async.commit_group;" ::: "memory")

__device__ __forceinline__ uint32_t h2_bits(__half2 h) {
    union { __half2 h; uint32_t u; } cv; cv.h = h; return cv.u;
}

__device__ __forceinline__ void mma_f16(float* d, const uint32_t* a, const uint32_t* b) {
    asm volatile("mma.sync.aligned.m16n8k16.row.col.f32.f16.f16.f32 "
        "{%0,%1,%2,%3}, {%4,%5,%6,%7}, {%8,%9}, {%0,%1,%2,%3};"
        : "+f"(d[0]), "+f"(d[1]), "+f"(d[2]), "+f"(d[3])
        : "r"(a[0]), "r"(a[1]), "r"(a[2]), "r"(a[3]), "r"(b[0]), "r"(b[1]));
}

#define LDSM_X4(r0, r1, r2, r3, addr) \
    asm volatile("ldmatrix.sync.aligned.m8n8.x4.shared.b16 {%0,%1,%2,%3}, [%4];" \
        : "=r"(r0), "=r"(r1), "=r"(r2), "=r"(r3) : "r"(addr))

// ---------------------------------------------------------------------------
// f32 -> fp16 conversion pre-pass
// ---------------------------------------------------------------------------
__global__ __launch_bounds__(256)
void gdn_convh_kernel(const float* __restrict__ src, uint4* __restrict__ dst, int n8) {
    int i = blockIdx.x * 256 + threadIdx.x;
    const int stride = gridDim.x * 256;
    const float4* s = (const float4*)src;
    for (; i < n8; i += stride) {
        float4 a = s[2*i], b = s[2*i+1];
        uint4 o;
        o.x = h2_bits(__floats2half2_rn(a.x, a.y));
        o.y = h2_bits(__floats2half2_rn(a.z, a.w));
        o.z = h2_bits(__floats2half2_rn(b.x, b.y));
        o.w = h2_bits(__floats2half2_rn(b.z, b.w));
        dst[i] = o;
    }
}

// ---------------------------------------------------------------------------
// Projection GEMM (round-11 shape: fp16 m16n8k16 + ldmatrix.x4).
// BM=BN=128, BK=32 halves, 3-stage cp.async ring, 256 thr, warp tile 32x64,
// 2 CTAs/SM. Single barrier per mainloop iteration.
// ---------------------------------------------------------------------------
#define RS   40
#define STG_H (128*RS)
#define STG_BYTES (STG_H*2)
#define GEMM_SMEM (3*2*STG_BYTES)

__global__ __launch_bounds__(256, 2)
void gdn_proj_gemm() {
    extern __shared__ __align__(16) __half hsm[];

    const __half* X = g_xh;
    const __half* W; float* C;
    if (blockIdx.z == 0)      { W = g_wqh; C = g_q; }
    else if (blockIdx.z == 1) { W = g_wkh; C = g_k; }
    else                      { W = g_wvh; C = g_v; }

    const int tid  = threadIdx.x;
    const int lane = tid & 31;
    const int wid  = tid >> 5;
    const int wm   = wid >> 1;
    const int wn   = wid & 1;
    const int g    = lane >> 2;
    const int tig  = lane & 3;

    const int rowA = blockIdx.y * 128;
    const int rowB = blockIdx.x * 128;

    const int lrow = tid >> 2;
    const int lcb  = (tid & 3) * 16;
    const int lch  = (tid & 3) * 8;

    const uint32_t sb = smem_u32(hsm);

    const int l8 = lane & 7;
    const int aradd = ((lane >> 3) & 1) * 8;
    const int acadd = ((lane >> 4) & 1) * 16;
    uint32_t aoff[2];
    #pragma unroll
    for (int mt = 0; mt < 2; mt++)
        aoff[mt] = (uint32_t)(wm*32 + mt*16 + aradd + l8) * 80 + acadd;
    const int bradd = ((lane >> 4) & 1) * 8;
    const int bcadd = ((lane >> 3) & 1) * 16;
    uint32_t boff[4];
    #pragma unroll
    for (int p = 0; p < 4; p++)
        boff[p] = (uint32_t)(wn*64 + p*16 + bradd + l8) * 80 + bcadd;

    auto load_stage = [&](int kt) {
        const int s = kt % 3;
        const uint32_t abase = sb + s * 2 * STG_BYTES;
        const uint32_t bbase = abase + STG_BYTES;
        const int k0 = kt * 32;
        cp16(abase + (uint32_t)lrow * 80 + lcb,        X + (size_t)(rowA + lrow) * DD + k0 + lch);
        cp16(abase + (uint32_t)(lrow + 64) * 80 + lcb, X + (size_t)(rowA + lrow + 64) * DD + k0 + lch);
        cp16(bbase + (uint32_t)lrow * 80 + lcb,        W + (size_t)(rowB + lrow) * DD + k0 + lch);
        cp16(bbase + (uint32_t)(lrow + 64) * 80 + lcb, W + (size_t)(rowB + lrow + 64) * DD + k0 + lch);
        CP_COMMIT();
    };

    float acc[2][8][4];
    #pragma unroll
    for (int i = 0; i < 2; i++)
        #pragma unroll
        for (int j = 0; j < 8; j++)
            #pragma unroll
            for (int l = 0; l < 4; l++) acc[i][j][l] = 0.f;

    load_stage(0);
    load_stage(1);

    const int KT = DD / 32;   // 64
    for (int kt = 0; kt < KT; ++kt) {
        asm volatile("cp.async.wait_group 1;" ::: "memory");
        __syncthreads();
        // single barrier per iter: stage (kt+2)%3's previous readers finished
        // in iter kt-1, strictly before this barrier.
        if (kt + 2 < KT) load_stage(kt + 2); else CP_COMMIT();

        const int s = kt % 3;
        const uint32_t abase = sb + s * 2 * STG_BYTES;
        const uint32_t bbase = abase + STG_BYTES;

        #pragma unroll
        for (int kk2 = 0; kk2 < 16; kk2 += 8) {
            const uint32_t kb = kk2 * 4;
            uint32_t afr[2][4], bfr[8][2];
            LDSM_X4(afr[0][0], afr[0][1], afr[0][2], afr[0][3], abase + aoff[0] + kb);
            LDSM_X4(afr[1][0], afr[1][1], afr[1][2], afr[1][3], abase + aoff[1] + kb);
            #pragma unroll
            for (int p = 0; p < 4; p++)
                LDSM_X4(bfr[2*p][0], bfr[2*p][1], bfr[2*p+1][0], bfr[2*p+1][1],
                        bbase + boff[p] + kb);
            #pragma unroll
            for (int mt = 0; mt < 2; mt++)
                #pragma unroll
                for (int nt = 0; nt < 8; nt++)
                    mma_f16(acc[mt][nt], afr[mt], bfr[nt]);
        }
    }

    #pragma unroll
    for (int mt = 0; mt < 2; mt++) {
        #pragma unroll
        for (int nt = 0; nt < 8; nt++) {
            const int r  = rowA + wm*32 + mt*16 + g;
            const int cc = rowB + wn*64 + nt*8 + tig*2;
            *(float2*)(C + (size_t)r*HK + cc)       = make_float2(acc[mt][nt][0], acc[mt][nt][1]);
            *(float2*)(C + (size_t)(r + 8)*HK + cc) = make_float2(acc[mt][nt][2], acc[mt][nt][3]);
        }
    }
}

// ---------------------------------------------------------------------------
// alpha/beta: [4096,32] = X @ [Wa;Wb]^T, then sigmoid / softplus*K^-0.5.
// ---------------------------------------------------------------------------
__global__ __launch_bounds__(256)
void gdn_ab_kernel(const float* __restrict__ X,
                   const float* __restrict__ Wa, const float* __restrict__ ba,
                   const float* __restrict__ Wb, const float* __restrict__ bbv) {
    __shared__ float xs[64][36];
    __shared__ float ws[32][33];
    const int tid  = threadIdx.x;
    const int row0 = blockIdx.x * 64;
    const int c    = tid & 31;
    const int rg   = tid >> 5;

    float acc[8];
    #pragma unroll
    for (int i = 0; i < 8; i++) acc[i] = 0.f;

    for (int k0 = 0; k0 < DD; k0 += 32) {
        __syncthreads();
        #pragma unroll
        for (int i = 0; i < 2; i++) {
            const int f = tid + i*256;
            const int r = f >> 3, c4 = (f & 7)*4;
            float4 val = *(const float4*)(X + (size_t)(row0 + r)*DD + k0 + c4);
            *(float4*)&xs[r][c4] = val;
        }
        #pragma unroll
        for (int i = 0; i < 4; i++) {
            const int f = tid + i*256;
            const int o = f >> 5, kkk = f & 31;
            const float* wr = (o < 16) ? (Wa + (size_t)o*DD) : (Wb + (size_t)(o - 16)*DD);
            ws[kkk][o] = wr[k0 + kkk];
        }
        __syncthreads();
        #pragma unroll 4
        for (int kkk = 0; kkk < 32; ++kkk) {
            const float w = ws[kkk][c];
            #pragma unroll
            for (int i = 0; i < 8; i++) acc[i] = fmaf(xs[rg*8 + i][kkk], w, acc[i]);
        }
    }

    #pragma unroll
    for (int i = 0; i < 8; i++) {
        const int bt = row0 + rg*8 + i;
        if (c < 16) {
            const float z = acc[i] + ba[c];
            g_alpha[(size_t)bt*HHN + c] = 1.f / (1.f + expf(-z));
        } else {
            const int h = c - 16;
            const float z = acc[i] + bbv[h];
            const float sp = fmaxf(z, 0.f) + log1pf(expf(-fabsf(z)));
            g_beta[(size_t)bt*HHN + h] = sp * 0.088388347648318447f;
        }
    }
}

// ---------------------------------------------------------------------------
// l2norm of q,k rows + fused kq[bt,h] = dot(q_norm, k_norm). Warp per row.
// ---------------------------------------------------------------------------
__global__ __launch_bounds__(256)
void gdn_l2norm_kernel() {
    const int gw   = (blockIdx.x * 256 + threadIdx.x) >> 5;
    const int lane = threadIdx.x & 31;

    float4* pq = reinterpret_cast<float4*>(g_q) + (size_t)gw*32 + lane;
    float4* pk = reinterpret_cast<float4*>(g_k) + (size_t)gw*32 + lane;
    float4 vq = *pq;
    float4 vk = *pk;

    float sq = vq.x*vq.x + vq.y*vq.y + vq.z*vq.z + vq.w*vq.w;
    float sk = vk.x*vk.x + vk.y*vk.y + vk.z*vk.z + vk.w*vk.w;
    #pragma unroll
    for (int o = 16; o; o >>= 1) {
        sq += __shfl_xor_sync(0xffffffffu, sq, o);
        sk += __shfl_xor_sync(0xffffffffu, sk, o);
    }
    const float iq = 1.0f / fmaxf(sqrtf(sq), 1e-12f);
    const float ik = 1.0f / fmaxf(sqrtf(sk), 1e-12f);
    vq.x *= iq; vq.y *= iq; vq.z *= iq; vq.w *= iq;
    vk.x *= ik; vk.y *= ik; vk.z *= ik; vk.w *= ik;
    *pq = vq;
    *pk = vk;

    float d = vq.x*vk.x + vq.y*vk.y + vq.z*vk.z + vq.w*vk.w;
    #pragma unroll
    for (int o = 16; o; o >>= 1) d += __shfl_xor_sync(0xffffffffu, d, o);
    if (lane == 0) g_kq[gw] = d;
}

// ---------------------------------------------------------------------------
// Pairwise cross-dots for 8-step groups. Warp per (b,h,g):
//   cd[TRI(i,j)]      = k_i.k_j  (i<j)
//   cd[28 + TRI(i,j)] = k_i.q_j  (i<j)
// Runs AFTER l2norm (normalized vectors).
// ---------------------------------------------------------------------------
__global__ __launch_bounds__(256)
void gdn_cross_kernel() {
    const int gw   = (blockIdx.x * 256 + threadIdx.x) >> 5;  // (b*HHN+h)*NG8+g
    const int lane = threadIdx.x & 31;
    const int g = gw & (NG8 - 1);
    const int h = (gw >> 8) & (HHN - 1);
    const int b = gw >> 12;
    const int t0 = 8 * g;

    float4 kv[8], qv[8];
    #pragma unroll
    for (int i = 0; i < 8; i++) {
        kv[i] = ((const float4*)(g_k + (size_t)(b*TT + t0 + i)*HK + h*KKD))[lane];
        qv[i] = ((const float4*)(g_q + (size_t)(b*TT + t0 + i)*HK + h*KKD))[lane];
    }

    auto dot4 = [](float4 a, float4 b) {
        return a.x*b.x + a.y*b.y + a.z*b.z + a.w*b.w;
    };
    float dd[56];
    #pragma unroll
    for (int i = 0; i < 8; i++)
        #pragma unroll
        for (int j = 0; j < 8; j++)
            if (i < j) {
                dd[TRI(i,j)]      = dot4(kv[i], kv[j]);
                dd[28 + TRI(i,j)] = dot4(kv[i], qv[j]);
            }

    #pragma unroll
    for (int o = 16; o; o >>= 1)
        #pragma unroll
        for (int i = 0; i < 56; i++)
            dd[i] += __shfl_xor_sync(0xffffffffu, dd[i], o);

    if (lane == 0) {
        float* dst = g_cd + (size_t)gw * 56;
        #pragma unroll
        for (int i = 0; i < 14; i++)
            *(float4*)(dst + 4*i) = make_float4(dd[4*i], dd[4*i+1], dd[4*i+2], dd[4*i+3]);
    }
}

// ---------------------------------------------------------------------------
// Gated delta-rule scan v7: 8-step fused groups.
//  - CTA = 256 thr (8 warps) = 32 v-rows; grid (4,16,2) = 128 CTAs (1/SM).
//  - Per group: D_i = S.k_i, E_i = S.q_i (i=0..7) reduce CONCURRENTLY on
//    pre-update S: one 3-round shuffle cascade + one barrier per 8 steps.
//  - In-group propagation via precomputed pairwise dots:
//      tk[j] tracks s_i.k_j, tq[j] tracks s_i.q_j (init D_j, E_j):
//      u_i = b_i (v_i - a_i tk[i]);  o_i = a_i tq[i] + u_i kq_i
//      for j>i: tk[j] = a_i tk[j] + u_i K(i,j); tq[j] = a_i tq[j] + u_i X(i,j)
//  - S update: S = suf(0) S + sum_i (u_i suf(i+1)) k_i   (suf = suffix prod of a)
// ---------------------------------------------------------------------------
__device__ __forceinline__ ull f2fma(ull a, ull b, ull c) {
    ull d; asm("fma.rn.f32x2 %0, %1, %2, %3;" : "=l"(d) : "l"(a), "l"(b), "l"(c)); return d;
}
__device__ __forceinline__ ull f2mul(ull a, ull b) {
    ull d; asm("mul.rn.f32x2 %0, %1, %2;" : "=l"(d) : "l"(a), "l"(b)); return d;
}
__device__ __forceinline__ ull f2pack(float lo, float hi) {
    ull d; asm("mov.b64 %0, {%1, %2};" : "=l"(d) : "f"(lo), "f"(hi)); return d;
}
__device__ __forceinline__ float f2hsum(ull a) {
    float lo, hi; asm("mov.b64 {%0, %1}, %2;" : "=f"(lo), "=f"(hi) : "l"(a)); return lo + hi;
}

#define SLC 20   // floats per kg slice (16 data + 4 pad -> 80B stride)

__global__ __launch_bounds__(256, 1)
void gdn_scan_kernel(float* __restrict__ out) {
    // 16 vectors per stage: 0..7 = k_0..k_7, 8..15 = q_0..q_7
    __shared__ __align__(16) float buf[3][16][8*SLC];

    const int b    = blockIdx.z;
    const int h    = blockIdx.y;
    const int tid  = threadIdx.x;
    const int w    = tid >> 5;
    const int lane = tid & 31;
    const int vi   = lane >> 3;
    const int kg   = lane & 7;
    const int vrow = blockIdx.x*32 + w*4 + vi;

    const float* krow = g_k     + (size_t)b*TT*HK + h*KKD;
    const float* qrow = g_q     + (size_t)b*TT*HK + h*KKD;
    const float* vp   = g_v     + (size_t)b*TT*HK + h*VVD + vrow;
    const float* ap   = g_alpha + (size_t)b*TT*HHN + h;
    const float* bp   = g_beta  + (size_t)b*TT*HHN + h;
    const float* kqp  = g_kq    + (size_t)b*TT*HHN + h;
    const float* cdp  = g_cd    + (size_t)(b*HHN + h)*NG8*56;
    float*       op   = out     + (size_t)b*TT*HK + h*VVD + vrow;

    // staging: 16 vectors x 32 chunks = 512 chunks; 2 per thread
    auto stage = [&](int g, int s) {
        #pragma unroll
        for (int half = 0; half < 2; half++) {
            const int c = tid + half*256;
            const int vecid = c >> 5;          // 0..15
            const int sc = c & 31;
            const float* src = ((vecid < 8) ? krow + (size_t)(8*g + vecid)*HK
                                            : qrow + (size_t)(8*g + vecid - 8)*HK) + sc*4;
            float* dst = buf[s][vecid] + (sc >> 2)*SLC + (sc & 3)*4;
            cp16(smem_u32(dst), src);
        }
        CP_COMMIT();
    };

    stage(0, 0);
    stage(1, 1);

    ull S[8];
    #pragma unroll
    for (int i = 0; i < 8; i++) S[i] = 0;

    for (int g = 0; g < NG8; ++g) {
        asm volatile("cp.async.wait_group 1;" ::: "memory");
        __syncthreads();
        const int s = g % 3;
        if (g + 2 < NG8) stage(g + 2, (g + 2) % 3); else CP_COMMIT();

        const size_t t0 = (size_t)8*g;
        float vv[8], aa[8], bb[8], kq[8];
        #pragma unroll
        for (int i = 0; i < 8; i++) {
            vv[i] = vp[(t0+i)*HK];
            aa[i] = ap[(t0+i)*HHN];
            bb[i] = bp[(t0+i)*HHN];
            kq[i] = kqp[(t0+i)*HHN];
        }
        float cd[56];
        #pragma unroll
        for (int i = 0; i < 14; i++) {
            float4 t = *(const float4*)(cdp + (size_t)g*56 + 4*i);
            cd[4*i] = t.x; cd[4*i+1] = t.y; cd[4*i+2] = t.z; cd[4*i+3] = t.w;
        }

        const ull* kp[8];
        const ull* qp[8];
        #pragma unroll
        for (int i = 0; i < 8; i++) {
            kp[i] = (const ull*)(buf[s][i]     + kg*SLC);
            qp[i] = (const ull*)(buf[s][8 + i] + kg*SLC);
        }

        // 16 concurrent reductions on pre-update S
        ull dch[8], ech[8];
        #pragma unroll
        for (int i = 0; i < 8; i++) {
            dch[i] = f2mul(S[0], kp[i][0]);
            ech[i] = f2mul(S[0], qp[i][0]);
        }
        #pragma unroll
        for (int j = 1; j < 8; j++)
            #pragma unroll
            for (int i = 0; i < 8; i++) {
                dch[i] = f2fma(S[j], kp[i][j], dch[i]);
                ech[i] = f2fma(S[j], qp[i][j], ech[i]);
            }
        float tk[8], tq[8];
        #pragma unroll
        for (int i = 0; i < 8; i++) {
            tk[i] = f2hsum(dch[i]);
            tq[i] = f2hsum(ech[i]);
        }
        #pragma unroll
        for (int o = 1; o <= 4; o <<= 1)
            #pragma unroll
            for (int i = 0; i < 8; i++) {
                tk[i] += __shfl_xor_sync(0xffffffffu, tk[i], o);
                tq[i] += __shfl_xor_sync(0xffffffffu, tq[i], o);
            }

        // scalar 8-step recurrence
        float u[8], oo[8];
        #pragma unroll
        for (int i = 0; i < 8; i++) {
            u[i]  = bb[i] * (vv[i] - aa[i] * tk[i]);
            oo[i] = fmaf(u[i], kq[i], aa[i] * tq[i]);
            #pragma unroll
            for (int j = 0; j < 8; j++)
                if (j > i) {
                    tk[j] = fmaf(u[i], cd[TRI(i,j)],      aa[i] * tk[j]);
                    tq[j] = fmaf(u[i], cd[28 + TRI(i,j)], aa[i] * tq[j]);
                }
        }

        if (kg == 0) {
            #pragma unroll
            for (int i = 0; i < 8; i++)
                op[(t0 + i)*HK] = oo[i];
        }

        // suffix products: suf[i] = a_i * ... * a_7
        float suf[9];
        suf[8] = 1.f;
        #pragma unroll
        for (int i = 7; i >= 0; i--) suf[i] = aa[i] * suf[i+1];
        ull cS2 = f2pack(suf[0], suf[0]);
        ull cu[8];
        #pragma unroll
        for (int i = 0; i < 8; i++) {
            const float c = u[i] * suf[i+1];
            cu[i] = f2pack(c, c);
        }
        // S = suf0*S + sum_i cu_i * k_i   (K streamed again from smem)
        #pragma unroll
        for (int j = 0; j < 8; j++) {
            ull acc = f2mul(cS2, S[j]);
            #pragma unroll
            for (int i = 0; i < 8; i++)
                acc = f2fma(cu[i], kp[i][j], acc);
            S[j] = acc;
        }
    }
}

// ---------------------------------------------------------------------------
extern "C" void kernel_launch(void* const* d_in, const int* in_sizes, int n_in,
                              void* d_out, int out_size) {
    const float* x   = (const float*)d_in[0];
    const float* Wq  = (const float*)d_in[1];
    const float* Wk  = (const float*)d_in[2];
    const float* Wv  = (const float*)d_in[3];
    const float* Wa  = (const float*)d_in[4];
    const float* ba  = (const float*)d_in[5];
    const float* Wb  = (const float*)d_in[6];
    const float* bbv = (const float*)d_in[7];
    float* out = (float*)d_out;

    __half *xh, *wqh, *wkh, *wvh;
    cudaGetSymbolAddress((void**)&xh,  g_xh);
    cudaGetSymbolAddress((void**)&wqh, g_wqh);
    cudaGetSymbolAddress((void**)&wkh, g_wkh);
    cudaGetSymbolAddress((void**)&wvh, g_wvh);

    cudaFuncSetAttribute(gdn_proj_gemm, cudaFuncAttributeMaxDynamicSharedMemorySize, GEMM_SMEM);

    gdn_convh_kernel<<<1024, 256>>>(x,  (uint4*)xh,  BT*DD/8);
    gdn_convh_kernel<<<512,  256>>>(Wq, (uint4*)wqh, HK*DD/8);
    gdn_convh_kernel<<<512,  256>>>(Wk, (uint4*)wkh, HK*DD/8);
    gdn_convh_kernel<<<512,  256>>>(Wv, (uint4*)wvh, HK*DD/8);

    gdn_proj_gemm<<<dim3(HK/128, BT/128, 3), 256, GEMM_SMEM>>>();  // (16, 32, 3)
    gdn_ab_kernel<<<BT/64, 256>>>(x, Wa, ba, Wb, bbv);
    gdn_l2norm_kernel<<<(BT*HHN)/8, 256>>>();
    gdn_cross_kernel<<<(BB*HHN*NG8)/8, 256>>>();
    gdn_scan_kernel<<<dim3(4, HHN, BB), 256>>>(out);
}

// round 15
// speedup vs baseline: 1.1034x; 1.1034x over previous
#include <cuda_runtime.h>
#include <cuda_fp16.h>
#include <math.h>
#include <stdint.h>

typedef unsigned long long ull;

// Problem dims (fixed)
#define BB 2
#define TT 2048
#define DD 2048
#define HHN 16
#define KKD 128
#define VVD 128
#define BT  (BB*TT)     // 4096
#define HK  (HHN*KKD)   // 2048
#define NG4 512         // 4-step groups

// Scratch (device globals: no allocation allowed)
__device__ float g_q[BT*HK];
__device__ float g_k[BT*HK];
__device__ float g_v[BT*HK];
__device__ float g_alpha[BT*HHN];
__device__ float g_beta[BT*HHN];
__device__ float g_kq[BT*HHN];              // k_t . q_t
__device__ float g_cd[BB*HHN*NG4*12];       // per group: K12,K13,K14,K23,K24,K34,X12,X13,X14,X23,X24,X34
__device__ __half g_xh[BT*DD];
__device__ __half g_wqh[HK*DD];
__device__ __half g_wkh[HK*DD];
__device__ __half g_wvh[HK*DD];

// ---------------------------------------------------------------------------
// helpers
// ---------------------------------------------------------------------------
__device__ __forceinline__ uint32_t smem_u32(const void* p) {
    uint32_t a;
    asm("{ .reg .u64 t; cvta.to.shared.u64 t, %1; cvt.u32.u64 %0, t; }" : "=r"(a) : "l"(p));
    return a;
}
__device__ __forceinline__ void cp16(uint32_t dst, const void* src) {
    asm volatile("cp.async.cg.shared.global [%0], [%1], 16;" :: "r"(dst), "l"(src));
}
#define CP_COMMIT() asm volatile("cp.async.commit_group;" ::: "memory")

__device__ __forceinline__ uint32_t h2_bits(__half2 h) {
    union { __half2 h; uint32_t u; } cv; cv.h = h; return cv.u;
}

__device__ __forceinline__ void mma_f16(float* d, const uint32_t* a, const uint32_t* b) {
    asm volatile("mma.sync.aligned.m16n8k16.row.col.f32.f16.f16.f32 "
        "{%0,%1,%2,%3}, {%4,%5,%6,%7}, {%8,%9}, {%0,%1,%2,%3};"
        : "+f"(d[0]), "+f"(d[1]), "+f"(d[2]), "+f"(d[3])
        : "r"(a[0]), "r"(a[1]), "r"(a[2]), "r"(a[3]), "r"(b[0]), "r"(b[1]));
}

#define LDSM_X4(r0, r1, r2, r3, addr) \
    asm volatile("ldmatrix.sync.aligned.m8n8.x4.shared.b16 {%0,%1,%2,%3}, [%4];" \
        : "=r"(r0), "=r"(r1), "=r"(r2), "=r"(r3) : "r"(addr))

// ---------------------------------------------------------------------------
// f32 -> fp16 conversion pre-pass
// ---------------------------------------------------------------------------
__global__ __launch_bounds__(256)
void gdn_convh_kernel(const float* __restrict__ src, uint4* __restrict__ dst, int n8) {
    int i = blockIdx.x * 256 + threadIdx.x;
    const int stride = gridDim.x * 256;
    const float4* s = (const float4*)src;
    for (; i < n8; i += stride) {
        float4 a = s[2*i], b = s[2*i+1];
        uint4 o;
        o.x = h2_bits(__floats2half2_rn(a.x, a.y));
        o.y = h2_bits(__floats2half2_rn(a.z, a.w));
        o.z = h2_bits(__floats2half2_rn(b.x, b.y));
        o.w = h2_bits(__floats2half2_rn(b.z, b.w));
        dst[i] = o;
    }
}

// ---------------------------------------------------------------------------
// Projection GEMM (round-11 WIN shape + single barrier per iter):
// fp16 m16n8k16 + ldmatrix.x4, BM=BN=128, BK=32 halves, 3-stage cp.async ring,
// 256 thr, warp tile 32x64, 2 CTAs/SM.
// ---------------------------------------------------------------------------
#define RS   40
#define STG_H (128*RS)
#define STG_BYTES (STG_H*2)
#define GEMM_SMEM (3*2*STG_BYTES)

__global__ __launch_bounds__(256, 2)
void gdn_proj_gemm() {
    extern __shared__ __align__(16) __half hsm[];

    const __half* X = g_xh;
    const __half* W; float* C;
    if (blockIdx.z == 0)      { W = g_wqh; C = g_q; }
    else if (blockIdx.z == 1) { W = g_wkh; C = g_k; }
    else                      { W = g_wvh; C = g_v; }

    const int tid  = threadIdx.x;
    const int lane = tid & 31;
    const int wid  = tid >> 5;
    const int wm   = wid >> 1;
    const int wn   = wid & 1;
    const int g    = lane >> 2;
    const int tig  = lane & 3;

    const int rowA = blockIdx.y * 128;
    const int rowB = blockIdx.x * 128;

    const int lrow = tid >> 2;
    const int lcb  = (tid & 3) * 16;
    const int lch  = (tid & 3) * 8;

    const uint32_t sb = smem_u32(hsm);

    const int l8 = lane & 7;
    const int aradd = ((lane >> 3) & 1) * 8;
    const int acadd = ((lane >> 4) & 1) * 16;
    uint32_t aoff[2];
    #pragma unroll
    for (int mt = 0; mt < 2; mt++)
        aoff[mt] = (uint32_t)(wm*32 + mt*16 + aradd + l8) * 80 + acadd;
    const int bradd = ((lane >> 4) & 1) * 8;
    const int bcadd = ((lane >> 3) & 1) * 16;
    uint32_t boff[4];
    #pragma unroll
    for (int p = 0; p < 4; p++)
        boff[p] = (uint32_t)(wn*64 + p*16 + bradd + l8) * 80 + bcadd;

    auto load_stage = [&](int kt) {
        const int s = kt % 3;
        const uint32_t abase = sb + s * 2 * STG_BYTES;
        const uint32_t bbase = abase + STG_BYTES;
        const int k0 = kt * 32;
        cp16(abase + (uint32_t)lrow * 80 + lcb,        X + (size_t)(rowA + lrow) * DD + k0 + lch);
        cp16(abase + (uint32_t)(lrow + 64) * 80 + lcb, X + (size_t)(rowA + lrow + 64) * DD + k0 + lch);
        cp16(bbase + (uint32_t)lrow * 80 + lcb,        W + (size_t)(rowB + lrow) * DD + k0 + lch);
        cp16(bbase + (uint32_t)(lrow + 64) * 80 + lcb, W + (size_t)(rowB + lrow + 64) * DD + k0 + lch);
        CP_COMMIT();
    };

    float acc[2][8][4];
    #pragma unroll
    for (int i = 0; i < 2; i++)
        #pragma unroll
        for (int j = 0; j < 8; j++)
            #pragma unroll
            for (int l = 0; l < 4; l++) acc[i][j][l] = 0.f;

    load_stage(0);
    load_stage(1);

    const int KT = DD / 32;   // 64
    for (int kt = 0; kt < KT; ++kt) {
        asm volatile("cp.async.wait_group 1;" ::: "memory");
        __syncthreads();
        // single barrier per iter: stage (kt+2)%3's previous readers finished
        // in iter kt-1, strictly before every thread passed this barrier.
        if (kt + 2 < KT) load_stage(kt + 2); else CP_COMMIT();

        const int s = kt % 3;
        const uint32_t abase = sb + s * 2 * STG_BYTES;
        const uint32_t bbase = abase + STG_BYTES;

        #pragma unroll
        for (int kk2 = 0; kk2 < 16; kk2 += 8) {
            const uint32_t kb = kk2 * 4;
            uint32_t afr[2][4], bfr[8][2];
            LDSM_X4(afr[0][0], afr[0][1], afr[0][2], afr[0][3], abase + aoff[0] + kb);
            LDSM_X4(afr[1][0], afr[1][1], afr[1][2], afr[1][3], abase + aoff[1] + kb);
            #pragma unroll
            for (int p = 0; p < 4; p++)
                LDSM_X4(bfr[2*p][0], bfr[2*p][1], bfr[2*p+1][0], bfr[2*p+1][1],
                        bbase + boff[p] + kb);
            #pragma unroll
            for (int mt = 0; mt < 2; mt++)
                #pragma unroll
                for (int nt = 0; nt < 8; nt++)
                    mma_f16(acc[mt][nt], afr[mt], bfr[nt]);
        }
    }

    #pragma unroll
    for (int mt = 0; mt < 2; mt++) {
        #pragma unroll
        for (int nt = 0; nt < 8; nt++) {
            const int r  = rowA + wm*32 + mt*16 + g;
            const int cc = rowB + wn*64 + nt*8 + tig*2;
            *(float2*)(C + (size_t)r*HK + cc)       = make_float2(acc[mt][nt][0], acc[mt][nt][1]);
            *(float2*)(C + (size_t)(r + 8)*HK + cc) = make_float2(acc[mt][nt][2], acc[mt][nt][3]);
        }
    }
}

// ---------------------------------------------------------------------------
// alpha/beta: [4096,32] = X @ [Wa;Wb]^T, then sigmoid / softplus*K^-0.5.
// ---------------------------------------------------------------------------
__global__ __launch_bounds__(256)
void gdn_ab_kernel(const float* __restrict__ X,
                   const float* __restrict__ Wa, const float* __restrict__ ba,
                   const float* __restrict__ Wb, const float* __restrict__ bbv) {
    __shared__ float xs[64][36];
    __shared__ float ws[32][33];
    const int tid  = threadIdx.x;
    const int row0 = blockIdx.x * 64;
    const int c    = tid & 31;
    const int rg   = tid >> 5;

    float acc[8];
    #pragma unroll
    for (int i = 0; i < 8; i++) acc[i] = 0.f;

    for (int k0 = 0; k0 < DD; k0 += 32) {
        __syncthreads();
        #pragma unroll
        for (int i = 0; i < 2; i++) {
            const int f = tid + i*256;
            const int r = f >> 3, c4 = (f & 7)*4;
            float4 val = *(const float4*)(X + (size_t)(row0 + r)*DD + k0 + c4);
            *(float4*)&xs[r][c4] = val;
        }
        #pragma unroll
        for (int i = 0; i < 4; i++) {
            const int f = tid + i*256;
            const int o = f >> 5, kkk = f & 31;
            const float* wr = (o < 16) ? (Wa + (size_t)o*DD) : (Wb + (size_t)(o - 16)*DD);
            ws[kkk][o] = wr[k0 + kkk];
        }
        __syncthreads();
        #pragma unroll 4
        for (int kkk = 0; kkk < 32; ++kkk) {
            const float w = ws[kkk][c];
            #pragma unroll
            for (int i = 0; i < 8; i++) acc[i] = fmaf(xs[rg*8 + i][kkk], w, acc[i]);
        }
    }

    #pragma unroll
    for (int i = 0; i < 8; i++) {
        const int bt = row0 + rg*8 + i;
        if (c < 16) {
            const float z = acc[i] + ba[c];
            g_alpha[(size_t)bt*HHN + c] = 1.f / (1.f + expf(-z));
        } else {
            const int h = c - 16;
            const float z = acc[i] + bbv[h];
            const float sp = fmaxf(z, 0.f) + log1pf(expf(-fabsf(z)));
            g_beta[(size_t)bt*HHN + h] = sp * 0.088388347648318447f;
        }
    }
}

// ---------------------------------------------------------------------------
// Fused l2norm + kq-diag + pairwise cross-dots. Warp per (b,h,4-step group):
//  - normalize the group's 4 k and 4 q vectors (one float4/lane each),
//  - write normalized vectors back,
//  - kq[t] = k_t.q_t for the 4 steps,
//  - cd = {K12,K13,K14,K23,K24,K34, X12,X13,X14,X23,X24,X34} (k_i.k_j, k_i.q_j).
// One global read pass instead of two (replaces l2norm + cross kernels).
// ---------------------------------------------------------------------------
__global__ __launch_bounds__(256)
void gdn_norm_cross_kernel() {
    const int gw   = (blockIdx.x * 256 + threadIdx.x) >> 5;  // (b*HHN+h)*NG4+g
    const int lane = threadIdx.x & 31;
    const int g = gw & (NG4 - 1);
    const int h = (gw >> 9) & (HHN - 1);
    const int b = gw >> 13;
    const int t0 = 4 * g;

    float4* kp[4];
    float4* qp[4];
    float4 kv[4], qv[4];
    #pragma unroll
    for (int i = 0; i < 4; i++) {
        kp[i] = (float4*)(g_k + (size_t)(b*TT + t0 + i)*HK + h*KKD) + lane;
        qp[i] = (float4*)(g_q + (size_t)(b*TT + t0 + i)*HK + h*KKD) + lane;
        kv[i] = *kp[i];
        qv[i] = *qp[i];
    }

    auto dot4 = [](float4 a, float4 b) {
        return a.x*b.x + a.y*b.y + a.z*b.z + a.w*b.w;
    };

    // phase 1: 8 squared norms, concurrent shuffle reductions
    float nn[8];
    #pragma unroll
    for (int i = 0; i < 4; i++) {
        nn[i]   = dot4(kv[i], kv[i]);
        nn[4+i] = dot4(qv[i], qv[i]);
    }
    #pragma unroll
    for (int o = 16; o; o >>= 1)
        #pragma unroll
        for (int i = 0; i < 8; i++)
            nn[i] += __shfl_xor_sync(0xffffffffu, nn[i], o);

    #pragma unroll
    for (int i = 0; i < 4; i++) {
        const float ik = 1.0f / fmaxf(sqrtf(nn[i]),   1e-12f);
        const float iq = 1.0f / fmaxf(sqrtf(nn[4+i]), 1e-12f);
        kv[i].x *= ik; kv[i].y *= ik; kv[i].z *= ik; kv[i].w *= ik;
        qv[i].x *= iq; qv[i].y *= iq; qv[i].z *= iq; qv[i].w *= iq;
        *kp[i] = kv[i];
        *qp[i] = qv[i];
    }

    // phase 2: 4 diag kq + 12 cross dots, concurrent reductions
    float dd[16];
    dd[0]  = dot4(kv[0], qv[0]); dd[1]  = dot4(kv[1], qv[1]);
    dd[2]  = dot4(kv[2], qv[2]); dd[3]  = dot4(kv[3], qv[3]);
    dd[4]  = dot4(kv[0], kv[1]); dd[5]  = dot4(kv[0], kv[2]);
    dd[6]  = dot4(kv[0], kv[3]); dd[7]  = dot4(kv[1], kv[2]);
    dd[8]  = dot4(kv[1], kv[3]); dd[9]  = dot4(kv[2], kv[3]);
    dd[10] = dot4(kv[0], qv[1]); dd[11] = dot4(kv[0], qv[2]);
    dd[12] = dot4(kv[0], qv[3]); dd[13] = dot4(kv[1], qv[2]);
    dd[14] = dot4(kv[1], qv[3]); dd[15] = dot4(kv[2], qv[3]);
    #pragma unroll
    for (int o = 16; o; o >>= 1)
        #pragma unroll
        for (int i = 0; i < 16; i++)
            dd[i] += __shfl_xor_sync(0xffffffffu, dd[i], o);

    if (lane == 0) {
        float* kqd = g_kq + (size_t)(b*TT + t0)*HHN + h;
        kqd[0]       = dd[0];
        kqd[HHN]     = dd[1];
        kqd[2*HHN]   = dd[2];
        kqd[3*HHN]   = dd[3];
        float* dst = g_cd + (size_t)gw * 12;
        *(float4*)(dst    ) = make_float4(dd[4],  dd[5],  dd[6],  dd[7]);
        *(float4*)(dst + 4) = make_float4(dd[8],  dd[9],  dd[10], dd[11]);
        *(float4*)(dst + 8) = make_float4(dd[12], dd[13], dd[14], dd[15]);
    }
}

// ---------------------------------------------------------------------------
// Gated delta-rule scan v6 (round-11 WIN, unchanged): 4-step fused groups.
// ---------------------------------------------------------------------------
__device__ __forceinline__ ull f2fma(ull a, ull b, ull c) {
    ull d; asm("fma.rn.f32x2 %0, %1, %2, %3;" : "=l"(d) : "l"(a), "l"(b), "l"(c)); return d;
}
__device__ __forceinline__ ull f2mul(ull a, ull b) {
    ull d; asm("mul.rn.f32x2 %0, %1, %2;" : "=l"(d) : "l"(a), "l"(b)); return d;
}
__device__ __forceinline__ ull f2pack(float lo, float hi) {
    ull d; asm("mov.b64 %0, {%1, %2};" : "=l"(d) : "f"(lo), "f"(hi)); return d;
}
__device__ __forceinline__ float f2hsum(ull a) {
    float lo, hi; asm("mov.b64 {%0, %1}, %2;" : "=f"(lo), "=f"(hi) : "l"(a)); return lo + hi;
}

#define SLC 20   // floats per kg slice (16 data + 4 pad -> 80B stride)

__global__ __launch_bounds__(256, 1)
void gdn_scan_kernel(float* __restrict__ out) {
    __shared__ __align__(16) float kbuf[3][4][8*SLC];
    __shared__ __align__(16) float qbuf[3][4][8*SLC];

    const int b    = blockIdx.z;
    const int h    = blockIdx.y;
    const int tid  = threadIdx.x;
    const int w    = tid >> 5;
    const int lane = tid & 31;
    const int vi   = lane >> 3;
    const int kg   = lane & 7;
    const int vrow = blockIdx.x*32 + w*4 + vi;

    const float* krow = g_k     + (size_t)b*TT*HK + h*KKD;
    const float* qrow = g_q     + (size_t)b*TT*HK + h*KKD;
    const float* vp   = g_v     + (size_t)b*TT*HK + h*VVD + vrow;
    const float* ap   = g_alpha + (size_t)b*TT*HHN + h;
    const float* bp   = g_beta  + (size_t)b*TT*HHN + h;
    const float* kqp  = g_kq    + (size_t)b*TT*HHN + h;
    const float* cdp  = g_cd    + (size_t)(b*HHN + h)*NG4*12;
    float*       op   = out     + (size_t)b*TT*HK + h*VVD + vrow;

    const int vec = tid >> 5;
    const int sc  = tid & 31;

    auto stage = [&](int g, int s) {
        const float* src = ((vec < 4) ? krow : qrow) + (size_t)(4*g + (vec & 3))*HK + sc*4;
        float* dst = ((vec < 4) ? kbuf[s][vec & 3] : qbuf[s][vec & 3])
                     + (sc >> 2)*SLC + (sc & 3)*4;
        cp16(smem_u32(dst), src);
        CP_COMMIT();
    };

    stage(0, 0);
    stage(1, 1);

    ull S[8];
    #pragma unroll
    for (int i = 0; i < 8; i++) S[i] = 0;

    for (int g = 0; g < NG4; ++g) {
        asm volatile("cp.async.wait_group 1;" ::: "memory");
        __syncthreads();
        const int s = g % 3;
        if (g + 2 < NG4) stage(g + 2, (g + 2) % 3); else CP_COMMIT();

        const size_t t0 = (size_t)4*g;
        const float v1 = vp[t0*HK],      v2 = vp[(t0+1)*HK];
        const float v3 = vp[(t0+2)*HK],  v4 = vp[(t0+3)*HK];
        const float a1 = ap[t0*HHN],     a2 = ap[(t0+1)*HHN];
        const float a3 = ap[(t0+2)*HHN], a4 = ap[(t0+3)*HHN];
        const float b1 = bp[t0*HHN],     b2 = bp[(t0+1)*HHN];
        const float b3 = bp[(t0+2)*HHN], b4 = bp[(t0+3)*HHN];
        const float kq1 = kqp[t0*HHN],     kq2 = kqp[(t0+1)*HHN];
        const float kq3 = kqp[(t0+2)*HHN], kq4 = kqp[(t0+3)*HHN];
        const float4 cda = *(const float4*)(cdp + (size_t)g*12);
        const float4 cdb = *(const float4*)(cdp + (size_t)g*12 + 4);
        const float4 cdc = *(const float4*)(cdp + (size_t)g*12 + 8);
        const float K12 = cda.x, K13 = cda.y, K14 = cda.z, K23 = cda.w;
        const float K24 = cdb.x, K34 = cdb.y, X12 = cdb.z, X13 = cdb.w;
        const float X14 = cdc.x, X23 = cdc.y, X24 = cdc.z, X34 = cdc.w;

        const ull* k1p = (const ull*)(kbuf[s][0] + kg*SLC);
        const ull* k2p = (const ull*)(kbuf[s][1] + kg*SLC);
        const ull* k3p = (const ull*)(kbuf[s][2] + kg*SLC);
        const ull* k4p = (const ull*)(kbuf[s][3] + kg*SLC);
        const ull* q1p = (const ull*)(qbuf[s][0] + kg*SLC);
        const ull* q2p = (const ull*)(qbuf[s][1] + kg*SLC);
        const ull* q3p = (const ull*)(qbuf[s][2] + kg*SLC);
        const ull* q4p = (const ull*)(qbuf[s][3] + kg*SLC);

        ull K1[8], K2[8], K3[8], K4[8];
        #pragma unroll
        for (int j = 0; j < 8; j++) {
            K1[j] = k1p[j]; K2[j] = k2p[j]; K3[j] = k3p[j]; K4[j] = k4p[j];
        }

        ull d1 = f2mul(S[0], K1[0]), d2 = f2mul(S[0], K2[0]);
        ull d3 = f2mul(S[0], K3[0]), d4 = f2mul(S[0], K4[0]);
        ull e1 = f2mul(S[0], q1p[0]), e2 = f2mul(S[0], q2p[0]);
        ull e3 = f2mul(S[0], q3p[0]), e4 = f2mul(S[0], q4p[0]);
        #pragma unroll
        for (int j = 1; j < 8; j++) {
            d1 = f2fma(S[j], K1[j], d1); d2 = f2fma(S[j], K2[j], d2);
            d3 = f2fma(S[j], K3[j], d3); d4 = f2fma(S[j], K4[j], d4);
            e1 = f2fma(S[j], q1p[j], e1); e2 = f2fma(S[j], q2p[j], e2);
            e3 = f2fma(S[j], q3p[j], e3); e4 = f2fma(S[j], q4p[j], e4);
        }
        float D1 = f2hsum(d1), D2 = f2hsum(d2), D3 = f2hsum(d3), D4 = f2hsum(d4);
        float E1 = f2hsum(e1), E2 = f2hsum(e2), E3 = f2hsum(e3), E4 = f2hsum(e4);
        #pragma unroll
        for (int o = 1; o <= 4; o <<= 1) {
            D1 += __shfl_xor_sync(0xffffffffu, D1, o);
            D2 += __shfl_xor_sync(0xffffffffu, D2, o);
            D3 += __shfl_xor_sync(0xffffffffu, D3, o);
            D4 += __shfl_xor_sync(0xffffffffu, D4, o);
            E1 += __shfl_xor_sync(0xffffffffu, E1, o);
            E2 += __shfl_xor_sync(0xffffffffu, E2, o);
            E3 += __shfl_xor_sync(0xffffffffu, E3, o);
            E4 += __shfl_xor_sync(0xffffffffu, E4, o);
        }

        const float u1 = b1 * (v1 - a1 * D1);
        const float o1 = fmaf(u1, kq1, a1 * E1);
        const float s2k = fmaf(u1, K12, a1 * D2);
        const float u2  = b2 * (v2 - a2 * s2k);
        const float s2q = fmaf(u1, X12, a1 * E2);
        const float o2  = fmaf(u2, kq2, a2 * s2q);
        const float s3k = fmaf(u2, K23, a2 * fmaf(u1, K13, a1 * D3));
        const float u3  = b3 * (v3 - a3 * s3k);
        const float s3q = fmaf(u2, X23, a2 * fmaf(u1, X13, a1 * E3));
        const float o3  = fmaf(u3, kq3, a3 * s3q);
        const float s4k = fmaf(u3, K34, a3 * fmaf(u2, K24, a2 * fmaf(u1, K14, a1 * D4)));
        const float u4  = b4 * (v4 - a4 * s4k);
        const float s4q = fmaf(u3, X34, a3 * fmaf(u2, X24, a2 * fmaf(u1, X14, a1 * E4)));
        const float o4  = fmaf(u4, kq4, a4 * s4q);

        if (kg == 0) {
            op[(t0    )*HK] = o1;
            op[(t0 + 1)*HK] = o2;
            op[(t0 + 2)*HK] = o3;
            op[(t0 + 3)*HK] = o4;
        }

        const float a43   = a4 * a3;
        const float a432  = a43 * a2;
        const float cS    = a432 * a1;
        const float ck1   = a432 * u1;
        const float ck2   = a43 * u2;
        const float ck3   = a4 * u3;
        const ull cS2  = f2pack(cS,  cS);
        const ull ck12 = f2pack(ck1, ck1);
        const ull ck22 = f2pack(ck2, ck2);
        const ull ck32 = f2pack(ck3, ck3);
        const ull ck42 = f2pack(u4,  u4);
        #pragma unroll
        for (int j = 0; j < 8; j++)
            S[j] = f2fma(ck42, K4[j],
                   f2fma(ck32, K3[j],
                   f2fma(ck22, K2[j],
                   f2fma(ck12, K1[j], f2mul(cS2, S[j])))));
    }
}

// ---------------------------------------------------------------------------
extern "C" void kernel_launch(void* const* d_in, const int* in_sizes, int n_in,
                              void* d_out, int out_size) {
    const float* x   = (const float*)d_in[0];
    const float* Wq  = (const float*)d_in[1];
    const float* Wk  = (const float*)d_in[2];
    const float* Wv  = (const float*)d_in[3];
    const float* Wa  = (const float*)d_in[4];
    const float* ba  = (const float*)d_in[5];
    const float* Wb  = (const float*)d_in[6];
    const float* bbv = (const float*)d_in[7];
    float* out = (float*)d_out;

    __half *xh, *wqh, *wkh, *wvh;
    cudaGetSymbolAddress((void**)&xh,  g_xh);
    cudaGetSymbolAddress((void**)&wqh, g_wqh);
    cudaGetSymbolAddress((void**)&wkh, g_wkh);
    cudaGetSymbolAddress((void**)&wvh, g_wvh);

    cudaFuncSetAttribute(gdn_proj_gemm, cudaFuncAttributeMaxDynamicSharedMemorySize, GEMM_SMEM);

    gdn_convh_kernel<<<1024, 256>>>(x,  (uint4*)xh,  BT*DD/8);
    gdn_convh_kernel<<<512,  256>>>(Wq, (uint4*)wqh, HK*DD/8);
    gdn_convh_kernel<<<512,  256>>>(Wk, (uint4*)wkh, HK*DD/8);
    gdn_convh_kernel<<<512,  256>>>(Wv, (uint4*)wvh, HK*DD/8);

    gdn_proj_gemm<<<dim3(HK/128, BT/128, 3), 256, GEMM_SMEM>>>();  // (16, 32, 3)
    gdn_ab_kernel<<<BT/64, 256>>>(x, Wa, ba, Wb, bbv);
    gdn_norm_cross_kernel<<<(BB*HHN*NG4)/8, 256>>>();
    gdn_scan_kernel<<<dim3(4, HHN, BB), 256>>>(out);
}

// round 17
// speedup vs baseline: 1.1353x; 1.0289x over previous
#include <cuda_runtime.h>
#include <cuda_fp16.h>
#include <math.h>
#include <stdint.h>

typedef unsigned long long ull;

// Problem dims (fixed)
#define BB 2
#define TT 2048
#define DD 2048
#define HHN 16
#define KKD 128
#define VVD 128
#define BT  (BB*TT)     // 4096
#define HK  (HHN*KKD)   // 2048
#define NG4 512         // 4-step groups

// Scratch (device globals: no allocation allowed)
__device__ float g_q[BT*HK];
__device__ float g_k[BT*HK];
__device__ float g_v[BT*HK];
__device__ float g_alpha[BT*HHN];
__device__ float g_beta[BT*HHN];
__device__ float g_kq[BT*HHN];              // k_t . q_t
__device__ float g_cd[BB*HHN*NG4*12];       // per group: K12,K13,K14,K23,K24,K34,X12,X13,X14,X23,X24,X34
__device__ __half g_xh[BT*DD];
__device__ __half g_wqh[HK*DD];
__device__ __half g_wkh[HK*DD];
__device__ __half g_wvh[HK*DD];

// ---------------------------------------------------------------------------
// helpers
// ---------------------------------------------------------------------------
__device__ __forceinline__ uint32_t smem_u32(const void* p) {
    uint32_t a;
    asm("{ .reg .u64 t; cvta.to.shared.u64 t, %1; cvt.u32.u64 %0, t; }" : "=r"(a) : "l"(p));
    return a;
}
__device__ __forceinline__ void cp16(uint32_t dst, const void* src) {
    asm volatile("cp.async.cg.shared.global [%0], [%1], 16;" :: "r"(dst), "l"(src));
}
#define CP_COMMIT() asm volatile("cp.async.commit_group;" ::: "memory")

__device__ __forceinline__ uint32_t h2_bits(__half2 h) {
    union { __half2 h; uint32_t u; } cv; cv.h = h; return cv.u;
}

__device__ __forceinline__ void mma_f16(float* d, const uint32_t* a, const uint32_t* b) {
    asm volatile("mma.sync.aligned.m16n8k16.row.col.f32.f16.f16.f32 "
        "{%0,%1,%2,%3}, {%4,%5,%6,%7}, {%8,%9}, {%0,%1,%2,%3};"
        : "+f"(d[0]), "+f"(d[1]), "+f"(d[2]), "+f"(d[3])
        : "r"(a[0]), "r"(a[1]), "r"(a[2]), "r"(a[3]), "r"(b[0]), "r"(b[1]));
}

#define LDSM_X4(r0, r1, r2, r3, addr) \
    asm volatile("ldmatrix.sync.aligned.m8n8.x4.shared.b16 {%0,%1,%2,%3}, [%4];" \
        : "=r"(r0), "=r"(r1), "=r"(r2), "=r"(r3) : "r"(addr))

// ---------------------------------------------------------------------------
// f32 -> fp16 conversion pre-pass
// ---------------------------------------------------------------------------
__global__ __launch_bounds__(256)
void gdn_convh_kernel(const float* __restrict__ src, uint4* __restrict__ dst, int n8) {
    int i = blockIdx.x * 256 + threadIdx.x;
    const int stride = gridDim.x * 256;
    const float4* s = (const float4*)src;
    for (; i < n8; i += stride) {
        float4 a = s[2*i], b = s[2*i+1];
        uint4 o;
        o.x = h2_bits(__floats2half2_rn(a.x, a.y));
        o.y = h2_bits(__floats2half2_rn(a.z, a.w));
        o.z = h2_bits(__floats2half2_rn(b.x, b.y));
        o.w = h2_bits(__floats2half2_rn(b.z, b.w));
        dst[i] = o;
    }
}

// ---------------------------------------------------------------------------
// Projection GEMM: fp16 m16n8k16 + ldmatrix.x4, BM=BN=128, BK=32 halves,
// 4-stage cp.async ring with wait_group 2 (two load-groups in flight),
// 256 thr, warp tile 32x64, 2 CTAs/SM, single barrier per iter.
// ---------------------------------------------------------------------------
#define RS   40
#define STG_H (128*RS)
#define STG_BYTES (STG_H*2)
#define GEMM_SMEM (4*2*STG_BYTES)     // 81920

__global__ __launch_bounds__(256, 2)
void gdn_proj_gemm() {
    extern __shared__ __align__(16) __half hsm[];

    const __half* X = g_xh;
    const __half* W; float* C;
    if (blockIdx.z == 0)      { W = g_wqh; C = g_q; }
    else if (blockIdx.z == 1) { W = g_wkh; C = g_k; }
    else                      { W = g_wvh; C = g_v; }

    const int tid  = threadIdx.x;
    const int lane = tid & 31;
    const int wid  = tid >> 5;
    const int wm   = wid >> 1;
    const int wn   = wid & 1;
    const int g    = lane >> 2;
    const int tig  = lane & 3;

    const int rowA = blockIdx.y * 128;
    const int rowB = blockIdx.x * 128;

    const int lrow = tid >> 2;
    const int lcb  = (tid & 3) * 16;
    const int lch  = (tid & 3) * 8;

    const uint32_t sb = smem_u32(hsm);

    const int l8 = lane & 7;
    const int aradd = ((lane >> 3) & 1) * 8;
    const int acadd = ((lane >> 4) & 1) * 16;
    uint32_t aoff[2];
    #pragma unroll
    for (int mt = 0; mt < 2; mt++)
        aoff[mt] = (uint32_t)(wm*32 + mt*16 + aradd + l8) * 80 + acadd;
    const int bradd = ((lane >> 4) & 1) * 8;
    const int bcadd = ((lane >> 3) & 1) * 16;
    uint32_t boff[4];
    #pragma unroll
    for (int p = 0; p < 4; p++)
        boff[p] = (uint32_t)(wn*64 + p*16 + bradd + l8) * 80 + bcadd;

    auto load_stage = [&](int kt) {
        const int s = kt & 3;
        const uint32_t abase = sb + s * 2 * STG_BYTES;
        const uint32_t bbase = abase + STG_BYTES;
        const int k0 = kt * 32;
        cp16(abase + (uint32_t)lrow * 80 + lcb,        X + (size_t)(rowA + lrow) * DD + k0 + lch);
        cp16(abase + (uint32_t)(lrow + 64) * 80 + lcb, X + (size_t)(rowA + lrow + 64) * DD + k0 + lch);
        cp16(bbase + (uint32_t)lrow * 80 + lcb,        W + (size_t)(rowB + lrow) * DD + k0 + lch);
        cp16(bbase + (uint32_t)(lrow + 64) * 80 + lcb, W + (size_t)(rowB + lrow + 64) * DD + k0 + lch);
        CP_COMMIT();
    };

    float acc[2][8][4];
    #pragma unroll
    for (int i = 0; i < 2; i++)
        #pragma unroll
        for (int j = 0; j < 8; j++)
            #pragma unroll
            for (int l = 0; l < 4; l++) acc[i][j][l] = 0.f;

    load_stage(0);
    load_stage(1);
    load_stage(2);

    const int KT = DD / 32;   // 64
    for (int kt = 0; kt < KT; ++kt) {
        asm volatile("cp.async.wait_group 2;" ::: "memory");
        __syncthreads();
        // slot (kt+3)&3 was last read in iter kt-1 (completed before this barrier),
        // and is disjoint from reader slot kt&3 and in-flight kt+1, kt+2.
        if (kt + 3 < KT) load_stage(kt + 3); else CP_COMMIT();

        const int s = kt & 3;
        const uint32_t abase = sb + s * 2 * STG_BYTES;
        const uint32_t bbase = abase + STG_BYTES;

        #pragma unroll
        for (int kk2 = 0; kk2 < 16; kk2 += 8) {
            const uint32_t kb = kk2 * 4;
            uint32_t afr[2][4], bfr[8][2];
            LDSM_X4(afr[0][0], afr[0][1], afr[0][2], afr[0][3], abase + aoff[0] + kb);
            LDSM_X4(afr[1][0], afr[1][1], afr[1][2], afr[1][3], abase + aoff[1] + kb);
            #pragma unroll
            for (int p = 0; p < 4; p++)
                LDSM_X4(bfr[2*p][0], bfr[2*p][1], bfr[2*p+1][0], bfr[2*p+1][1],
                        bbase + boff[p] + kb);
            #pragma unroll
            for (int mt = 0; mt < 2; mt++)
                #pragma unroll
                for (int nt = 0; nt < 8; nt++)
                    mma_f16(acc[mt][nt], afr[mt], bfr[nt]);
        }
    }

    #pragma unroll
    for (int mt = 0; mt < 2; mt++) {
        #pragma unroll
        for (int nt = 0; nt < 8; nt++) {
            const int r  = rowA + wm*32 + mt*16 + g;
            const int cc = rowB + wn*64 + nt*8 + tig*2;
            *(float2*)(C + (size_t)r*HK + cc)       = make_float2(acc[mt][nt][0], acc[mt][nt][1]);
            *(float2*)(C + (size_t)(r + 8)*HK + cc) = make_float2(acc[mt][nt][2], acc[mt][nt][3]);
        }
    }
}

// ---------------------------------------------------------------------------
// alpha/beta: [4096,32] = X @ [Wa;Wb]^T, then sigmoid / softplus*K^-0.5.
// ---------------------------------------------------------------------------
__global__ __launch_bounds__(256)
void gdn_ab_kernel(const float* __restrict__ X,
                   const float* __restrict__ Wa, const float* __restrict__ ba,
                   const float* __restrict__ Wb, const float* __restrict__ bbv) {
    __shared__ float xs[64][36];
    __shared__ float ws[32][33];
    const int tid  = threadIdx.x;
    const int row0 = blockIdx.x * 64;
    const int c    = tid & 31;
    const int rg   = tid >> 5;

    float acc[8];
    #pragma unroll
    for (int i = 0; i < 8; i++) acc[i] = 0.f;

    for (int k0 = 0; k0 < DD; k0 += 32) {
        __syncthreads();
        #pragma unroll
        for (int i = 0; i < 2; i++) {
            const int f = tid + i*256;
            const int r = f >> 3, c4 = (f & 7)*4;
            float4 val = *(const float4*)(X + (size_t)(row0 + r)*DD + k0 + c4);
            *(float4*)&xs[r][c4] = val;
        }
        #pragma unroll
        for (int i = 0; i < 4; i++) {
            const int f = tid + i*256;
            const int o = f >> 5, kkk = f & 31;
            const float* wr = (o < 16) ? (Wa + (size_t)o*DD) : (Wb + (size_t)(o - 16)*DD);
            ws[kkk][o] = wr[k0 + kkk];
        }
        __syncthreads();
        #pragma unroll 4
        for (int kkk = 0; kkk < 32; ++kkk) {
            const float w = ws[kkk][c];
            #pragma unroll
            for (int i = 0; i < 8; i++) acc[i] = fmaf(xs[rg*8 + i][kkk], w, acc[i]);
        }
    }

    #pragma unroll
    for (int i = 0; i < 8; i++) {
        const int bt = row0 + rg*8 + i;
        if (c < 16) {
            const float z = acc[i] + ba[c];
            g_alpha[(size_t)bt*HHN + c] = 1.f / (1.f + expf(-z));
        } else {
            const int h = c - 16;
            const float z = acc[i] + bbv[h];
            const float sp = fmaxf(z, 0.f) + log1pf(expf(-fabsf(z)));
            g_beta[(size_t)bt*HHN + h] = sp * 0.088388347648318447f;
        }
    }
}

// ---------------------------------------------------------------------------
// Fused l2norm + kq-diag + pairwise cross-dots. Warp per (b,h,4-step group).
// ---------------------------------------------------------------------------
__global__ __launch_bounds__(256)
void gdn_norm_cross_kernel() {
    const int gw   = (blockIdx.x * 256 + threadIdx.x) >> 5;  // (b*HHN+h)*NG4+g
    const int lane = threadIdx.x & 31;
    const int g = gw & (NG4 - 1);
    const int h = (gw >> 9) & (HHN - 1);
    const int b = gw >> 13;
    const int t0 = 4 * g;

    float4* kp[4];
    float4* qp[4];
    float4 kv[4], qv[4];
    #pragma unroll
    for (int i = 0; i < 4; i++) {
        kp[i] = (float4*)(g_k + (size_t)(b*TT + t0 + i)*HK + h*KKD) + lane;
        qp[i] = (float4*)(g_q + (size_t)(b*TT + t0 + i)*HK + h*KKD) + lane;
        kv[i] = *kp[i];
        qv[i] = *qp[i];
    }

    auto dot4 = [](float4 a, float4 b) {
        return a.x*b.x + a.y*b.y + a.z*b.z + a.w*b.w;
    };

    float nn[8];
    #pragma unroll
    for (int i = 0; i < 4; i++) {
        nn[i]   = dot4(kv[i], kv[i]);
        nn[4+i] = dot4(qv[i], qv[i]);
    }
    #pragma unroll
    for (int o = 16; o; o >>= 1)
        #pragma unroll
        for (int i = 0; i < 8; i++)
            nn[i] += __shfl_xor_sync(0xffffffffu, nn[i], o);

    #pragma unroll
    for (int i = 0; i < 4; i++) {
        const float ik = 1.0f / fmaxf(sqrtf(nn[i]),   1e-12f);
        const float iq = 1.0f / fmaxf(sqrtf(nn[4+i]), 1e-12f);
        kv[i].x *= ik; kv[i].y *= ik; kv[i].z *= ik; kv[i].w *= ik;
        qv[i].x *= iq; qv[i].y *= iq; qv[i].z *= iq; qv[i].w *= iq;
        *kp[i] = kv[i];
        *qp[i] = qv[i];
    }

    float dd[16];
    dd[0]  = dot4(kv[0], qv[0]); dd[1]  = dot4(kv[1], qv[1]);
    dd[2]  = dot4(kv[2], qv[2]); dd[3]  = dot4(kv[3], qv[3]);
    dd[4]  = dot4(kv[0], kv[1]); dd[5]  = dot4(kv[0], kv[2]);
    dd[6]  = dot4(kv[0], kv[3]); dd[7]  = dot4(kv[1], kv[2]);
    dd[8]  = dot4(kv[1], kv[3]); dd[9]  = dot4(kv[2], kv[3]);
    dd[10] = dot4(kv[0], qv[1]); dd[11] = dot4(kv[0], qv[2]);
    dd[12] = dot4(kv[0], qv[3]); dd[13] = dot4(kv[1], qv[2]);
    dd[14] = dot4(kv[1], qv[3]); dd[15] = dot4(kv[2], qv[3]);
    #pragma unroll
    for (int o = 16; o; o >>= 1)
        #pragma unroll
        for (int i = 0; i < 16; i++)
            dd[i] += __shfl_xor_sync(0xffffffffu, dd[i], o);

    if (lane == 0) {
        float* kqd = g_kq + (size_t)(b*TT + t0)*HHN + h;
        kqd[0]       = dd[0];
        kqd[HHN]     = dd[1];
        kqd[2*HHN]   = dd[2];
        kqd[3*HHN]   = dd[3];
        float* dst = g_cd + (size_t)gw * 12;
        *(float4*)(dst    ) = make_float4(dd[4],  dd[5],  dd[6],  dd[7]);
        *(float4*)(dst + 4) = make_float4(dd[8],  dd[9],  dd[10], dd[11]);
        *(float4*)(dst + 8) = make_float4(dd[12], dd[13], dd[14], dd[15]);
    }
}

// ---------------------------------------------------------------------------
// Gated delta-rule scan v6b: 4-step fused groups, 2 CTAs/SM.
//  - CTA = 128 thr (4 warps) = 16 v-rows; grid (8,16,2) = 256 CTAs.
//    Two independent CTAs per SM overlap their barrier-synced serial chains.
// ---------------------------------------------------------------------------
__device__ __forceinline__ ull f2fma(ull a, ull b, ull c) {
    ull d; asm("fma.rn.f32x2 %0, %1, %2, %3;" : "=l"(d) : "l"(a), "l"(b), "l"(c)); return d;
}
__device__ __forceinline__ ull f2mul(ull a, ull b) {
    ull d; asm("mul.rn.f32x2 %0, %1, %2;" : "=l"(d) : "l"(a), "l"(b)); return d;
}
__device__ __forceinline__ ull f2pack(float lo, float hi) {
    ull d; asm("mov.b64 %0, {%1, %2};" : "=l"(d) : "f"(lo), "f"(hi)); return d;
}
__device__ __forceinline__ float f2hsum(ull a) {
    float lo, hi; asm("mov.b64 {%0, %1}, %2;" : "=f"(lo), "=f"(hi) : "l"(a)); return lo + hi;
}

#define SLC 20   // floats per kg slice (16 data + 4 pad -> 80B stride)

__global__ __launch_bounds__(128, 2)
void gdn_scan_kernel(float* __restrict__ out) {
    __shared__ __align__(16) float kbuf[3][4][8*SLC];
    __shared__ __align__(16) float qbuf[3][4][8*SLC];

    const int b    = blockIdx.z;
    const int h    = blockIdx.y;
    const int tid  = threadIdx.x;
    const int w    = tid >> 5;
    const int lane = tid & 31;
    const int vi   = lane >> 3;
    const int kg   = lane & 7;
    const int vrow = blockIdx.x*16 + w*4 + vi;

    const float* krow = g_k     + (size_t)b*TT*HK + h*KKD;
    const float* qrow = g_q     + (size_t)b*TT*HK + h*KKD;
    const float* vp   = g_v     + (size_t)b*TT*HK + h*VVD + vrow;
    const float* ap   = g_alpha + (size_t)b*TT*HHN + h;
    const float* bp   = g_beta  + (size_t)b*TT*HHN + h;
    const float* kqp  = g_kq    + (size_t)b*TT*HHN + h;
    const float* cdp  = g_cd    + (size_t)(b*HHN + h)*NG4*12;
    float*       op   = out     + (size_t)b*TT*HK + h*VVD + vrow;

    // staging: 8 vectors x 32 chunks = 256 chunks; 2 per thread (128 thr)
    auto stage = [&](int g, int s) {
        #pragma unroll
        for (int half = 0; half < 2; half++) {
            const int c = tid + half*128;
            const int vecid = c >> 5;          // 0..7
            const int sc = c & 31;
            const float* src = ((vecid < 4) ? krow + (size_t)(4*g + vecid)*HK
                                            : qrow + (size_t)(4*g + vecid - 4)*HK) + sc*4;
            float* dst = ((vecid < 4) ? kbuf[s][vecid] : qbuf[s][vecid - 4])
                         + (sc >> 2)*SLC + (sc & 3)*4;
            cp16(smem_u32(dst), src);
        }
        CP_COMMIT();
    };

    stage(0, 0);
    stage(1, 1);

    ull S[8];
    #pragma unroll
    for (int i = 0; i < 8; i++) S[i] = 0;

    for (int g = 0; g < NG4; ++g) {
        asm volatile("cp.async.wait_group 1;" ::: "memory");
        __syncthreads();
        const int s = g % 3;
        if (g + 2 < NG4) stage(g + 2, (g + 2) % 3); else CP_COMMIT();

        const size_t t0 = (size_t)4*g;
        const float v1 = vp[t0*HK],      v2 = vp[(t0+1)*HK];
        const float v3 = vp[(t0+2)*HK],  v4 = vp[(t0+3)*HK];
        const float a1 = ap[t0*HHN],     a2 = ap[(t0+1)*HHN];
        const float a3 = ap[(t0+2)*HHN], a4 = ap[(t0+3)*HHN];
        const float b1 = bp[t0*HHN],     b2 = bp[(t0+1)*HHN];
        const float b3 = bp[(t0+2)*HHN], b4 = bp[(t0+3)*HHN];
        const float kq1 = kqp[t0*HHN],     kq2 = kqp[(t0+1)*HHN];
        const float kq3 = kqp[(t0+2)*HHN], kq4 = kqp[(t0+3)*HHN];
        const float4 cda = *(const float4*)(cdp + (size_t)g*12);
        const float4 cdb = *(const float4*)(cdp + (size_t)g*12 + 4);
        const float4 cdc = *(const float4*)(cdp + (size_t)g*12 + 8);
        const float K12 = cda.x, K13 = cda.y, K14 = cda.z, K23 = cda.w;
        const float K24 = cdb.x, K34 = cdb.y, X12 = cdb.z, X13 = cdb.w;
        const float X14 = cdc.x, X23 = cdc.y, X24 = cdc.z, X34 = cdc.w;

        const ull* k1p = (const ull*)(kbuf[s][0] + kg*SLC);
        const ull* k2p = (const ull*)(kbuf[s][1] + kg*SLC);
        const ull* k3p = (const ull*)(kbuf[s][2] + kg*SLC);
        const ull* k4p = (const ull*)(kbuf[s][3] + kg*SLC);
        const ull* q1p = (const ull*)(qbuf[s][0] + kg*SLC);
        const ull* q2p = (const ull*)(qbuf[s][1] + kg*SLC);
        const ull* q3p = (const ull*)(qbuf[s][2] + kg*SLC);
        const ull* q4p = (const ull*)(qbuf[s][3] + kg*SLC);

        ull K1[8], K2[8], K3[8], K4[8];
        #pragma unroll
        for (int j = 0; j < 8; j++) {
            K1[j] = k1p[j]; K2[j] = k2p[j]; K3[j] = k3p[j]; K4[j] = k4p[j];
        }

        ull d1 = f2mul(S[0], K1[0]), d2 = f2mul(S[0], K2[0]);
        ull d3 = f2mul(S[0], K3[0]), d4 = f2mul(S[0], K4[0]);
        ull e1 = f2mul(S[0], q1p[0]), e2 = f2mul(S[0], q2p[0]);
        ull e3 = f2mul(S[0], q3p[0]), e4 = f2mul(S[0], q4p[0]);
        #pragma unroll
        for (int j = 1; j < 8; j++) {
            d1 = f2fma(S[j], K1[j], d1); d2 = f2fma(S[j], K2[j], d2);
            d3 = f2fma(S[j], K3[j], d3); d4 = f2fma(S[j], K4[j], d4);
            e1 = f2fma(S[j], q1p[j], e1); e2 = f2fma(S[j], q2p[j], e2);
            e3 = f2fma(S[j], q3p[j], e3); e4 = f2fma(S[j], q4p[j], e4);
        }
        float D1 = f2hsum(d1), D2 = f2hsum(d2), D3 = f2hsum(d3), D4 = f2hsum(d4);
        float E1 = f2hsum(e1), E2 = f2hsum(e2), E3 = f2hsum(e3), E4 = f2hsum(e4);
        #pragma unroll
        for (int o = 1; o <= 4; o <<= 1) {
            D1 += __shfl_xor_sync(0xffffffffu, D1, o);
            D2 += __shfl_xor_sync(0xffffffffu, D2, o);
            D3 += __shfl_xor_sync(0xffffffffu, D3, o);
            D4 += __shfl_xor_sync(0xffffffffu, D4, o);
            E1 += __shfl_xor_sync(0xffffffffu, E1, o);
            E2 += __shfl_xor_sync(0xffffffffu, E2, o);
            E3 += __shfl_xor_sync(0xffffffffu, E3, o);
            E4 += __shfl_xor_sync(0xffffffffu, E4, o);
        }

        const float u1 = b1 * (v1 - a1 * D1);
        const float o1 = fmaf(u1, kq1, a1 * E1);
        const float s2k = fmaf(u1, K12, a1 * D2);
        const float u2  = b2 * (v2 - a2 * s2k);
        const float s2q = fmaf(u1, X12, a1 * E2);
        const float o2  = fmaf(u2, kq2, a2 * s2q);
        const float s3k = fmaf(u2, K23, a2 * fmaf(u1, K13, a1 * D3));
        const float u3  = b3 * (v3 - a3 * s3k);
        const float s3q = fmaf(u2, X23, a2 * fmaf(u1, X13, a1 * E3));
        const float o3  = fmaf(u3, kq3, a3 * s3q);
        const float s4k = fmaf(u3, K34, a3 * fmaf(u2, K24, a2 * fmaf(u1, K14, a1 * D4)));
        const float u4  = b4 * (v4 - a4 * s4k);
        const float s4q = fmaf(u3, X34, a3 * fmaf(u2, X24, a2 * fmaf(u1, X14, a1 * E4)));
        const float o4  = fmaf(u4, kq4, a4 * s4q);

        if (kg == 0) {
            op[(t0    )*HK] = o1;
            op[(t0 + 1)*HK] = o2;
            op[(t0 + 2)*HK] = o3;
            op[(t0 + 3)*HK] = o4;
        }

        const float a43   = a4 * a3;
        const float a432  = a43 * a2;
        const float cS    = a432 * a1;
        const float ck1   = a432 * u1;
        const float ck2   = a43 * u2;
        const float ck3   = a4 * u3;
        const ull cS2  = f2pack(cS,  cS);
        const ull ck12 = f2pack(ck1, ck1);
        const ull ck22 = f2pack(ck2, ck2);
        const ull ck32 = f2pack(ck3, ck3);
        const ull ck42 = f2pack(u4,  u4);
        #pragma unroll
        for (int j = 0; j < 8; j++)
            S[j] = f2fma(ck42, K4[j],
                   f2fma(ck32, K3[j],
                   f2fma(ck22, K2[j],
                   f2fma(ck12, K1[j], f2mul(cS2, S[j])))));
    }
}

// ---------------------------------------------------------------------------
extern "C" void kernel_launch(void* const* d_in, const int* in_sizes, int n_in,
                              void* d_out, int out_size) {
    const float* x   = (const float*)d_in[0];
    const float* Wq  = (const float*)d_in[1];
    const float* Wk  = (const float*)d_in[2];
    const float* Wv  = (const float*)d_in[3];
    const float* Wa  = (const float*)d_in[4];
    const float* ba  = (const float*)d_in[5];
    const float* Wb  = (const float*)d_in[6];
    const float* bbv = (const float*)d_in[7];
    float* out = (float*)d_out;

    __half *xh, *wqh, *wkh, *wvh;
    cudaGetSymbolAddress((void**)&xh,  g_xh);
    cudaGetSymbolAddress((void**)&wqh, g_wqh);
    cudaGetSymbolAddress((void**)&wkh, g_wkh);
    cudaGetSymbolAddress((void**)&wvh, g_wvh);

    cudaFuncSetAttribute(gdn_proj_gemm, cudaFuncAttributeMaxDynamicSharedMemorySize, GEMM_SMEM);

    gdn_convh_kernel<<<1024, 256>>>(x,  (uint4*)xh,  BT*DD/8);
    gdn_convh_kernel<<<512,  256>>>(Wq, (uint4*)wqh, HK*DD/8);
    gdn_convh_kernel<<<512,  256>>>(Wk, (uint4*)wkh, HK*DD/8);
    gdn_convh_kernel<<<512,  256>>>(Wv, (uint4*)wvh, HK*DD/8);

    gdn_proj_gemm<<<dim3(HK/128, BT/128, 3), 256, GEMM_SMEM>>>();  // (16, 32, 3)
    gdn_ab_kernel<<<BT/64, 256>>>(x, Wa, ba, Wb, bbv);
    gdn_norm_cross_kernel<<<(BB*HHN*NG4)/8, 256>>>();
    gdn_scan_kernel<<<dim3(8, HHN, BB), 128>>>(out);
}